// round 6
// baseline (speedup 1.0000x reference)
#include <cuda_runtime.h>
#include <math.h>

#define N    2048
#define HID  16
#define TPB  256

typedef unsigned long long u64;

// Per-signal derived scalars, packed: [i*2+0]={t,ra,dec,mc}  [i*2+1]={f_isco,dist,psi,0}
__device__ float4 g_pre4[2 * N];
// exp(logit) matrix (16 MB, L2-resident). Symmetric; diagonal = 0.
__device__ float g_ew[N * N];
// Packed importance-net weights. Pairing: lo half = h, hi half = h+8 (h=0..7).
// g_wp[k*8+hp]  = pack(W1c[hp][k], W1c[hp+8][k])   (W1c = W1 - colmean)
// g_b1p[hp]     = pack(b1c[hp], b1c[hp+8])          (b1c = b1 - mean(b1))
// g_gp / g_btp  = packed ln gain / bias
// g_w2gp[hp]    = pack(w2*g)  (for folded linear-part dot)
// g_w05p[hp]    = pack(0.5*w2)
__device__ u64 g_wp[64];
__device__ u64 g_b1p[8], g_gp[8], g_btp[8], g_w2gp[8], g_w05p[8];
__device__ float g_cL[1];   // sum_h w2[h]*bt1[h]

__device__ __forceinline__ u64 pk2(float lo, float hi) {
    u64 r; asm("mov.b64 %0, {%1, %2};" : "=l"(r) : "f"(lo), "f"(hi)); return r;
}
__device__ __forceinline__ void upk2(u64 v, float& lo, float& hi) {
    asm("mov.b64 {%0, %1}, %2;" : "=f"(lo), "=f"(hi) : "l"(v));
}
__device__ __forceinline__ u64 fma2(u64 a, u64 b, u64 c) {
    u64 d; asm("fma.rn.f32x2 %0, %1, %2, %3;" : "=l"(d) : "l"(a), "l"(b), "l"(c)); return d;
}
__device__ __forceinline__ u64 mul2(u64 a, u64 b) {
    u64 d; asm("mul.rn.f32x2 %0, %1, %2;" : "=l"(d) : "l"(a), "l"(b)); return d;
}
__device__ __forceinline__ float rcpa(float x) {
    float r; asm("rcp.approx.f32 %0, %1;" : "=f"(r) : "f"(x)); return r;
}
__device__ __forceinline__ float ex2a(float x) {
    float r; asm("ex2.approx.f32 %0, %1;" : "=f"(r) : "f"(x)); return r;
}

__global__ void pre_kernel(const float* __restrict__ p,
                           const float* __restrict__ iw1, const float* __restrict__ ib1,
                           const float* __restrict__ ig1, const float* __restrict__ ibt1,
                           const float* __restrict__ iw2)
{
    __shared__ float s_col[8];
    __shared__ float s_bm;
    int tid = threadIdx.x;
    int i = blockIdx.x * blockDim.x + tid;
    if (i < N) {
        const float* pi = p + i * 15;
        float m1 = fmaf(pi[0], 95.f, 5.f);
        float m2 = fmaf(pi[1], 95.f, 5.f);
        float mc = __powf(m1 * m2, 0.6f) * __powf(m1 + m2, -0.2f);
        g_pre4[i * 2 + 0] = make_float4(pi[5], pi[3], pi[4], mc);
        g_pre4[i * 2 + 1] = make_float4(220.f / (m1 + m2), fmaf(pi[2], 2950.f, 50.f), pi[7], 0.f);
    }
    if (blockIdx.x == 0) {
        if (tid < 8) {
            float s = 0.f;
#pragma unroll
            for (int h = 0; h < HID; h++) s += iw1[h * 8 + tid];
            s_col[tid] = s * (1.f / HID);
        }
        if (tid == 0) {
            float bm = 0.f, cl = 0.f;
#pragma unroll
            for (int h = 0; h < HID; h++) { bm += ib1[h]; cl += iw2[h] * ibt1[h]; }
            s_bm = bm * (1.f / HID);
            g_cL[0] = cl;
        }
        __syncthreads();
        if (tid < 64) {
            int hp = tid & 7, k = tid >> 3;
            g_wp[k * 8 + hp] = pk2(iw1[hp * 8 + k] - s_col[k],
                                   iw1[(hp + 8) * 8 + k] - s_col[k]);
        }
        if (tid < 8) {
            int hp = tid;
            float bm = s_bm;
            g_b1p[hp]  = pk2(ib1[hp] - bm, ib1[hp + 8] - bm);
            g_gp[hp]   = pk2(ig1[hp], ig1[hp + 8]);
            g_btp[hp]  = pk2(ibt1[hp], ibt1[hp + 8]);
            g_w2gp[hp] = pk2(iw2[hp] * ig1[hp], iw2[hp + 8] * ig1[hp + 8]);
            g_w05p[hp] = pk2(0.5f * iw2[hp], 0.5f * iw2[hp + 8]);
        }
    }
}

// Fast erf-GELU (scalar, for the tiny overlap net only)
__device__ __forceinline__ float gelu_fast(float x) {
    float ax = fabsf(x) * 0.70710678118654752f;
    float u  = rcpa(fmaf(0.3275911f, ax, 1.f));
    float pl = fmaf(fmaf(fmaf(fmaf(1.061405429f, u, -1.453152027f),
                               u, 1.421413741f),
                          u, -0.284496736f),
                     u, 0.254829592f) * u;
    float e  = ex2a(-ax * ax * 1.44269504088896f);
    float er = fmaf(-pl, e, 1.f);
    er = copysignf(er, x);
    return 0.5f * x * (1.f + er);
}

// ---------------------------------------------------------------------------
// Kernel B: importance-net exp(logits), upper triangle only, packed f32x2.
// ---------------------------------------------------------------------------
__global__ __launch_bounds__(TPB) void logits_kernel(const float* __restrict__ ib2)
{
    __shared__ u64 s_wp[64];
    __shared__ u64 s_b1p[8], s_gp[8], s_btp[8], s_w2gp[8], s_w05p[8];

    const int tid = threadIdx.x;
    const int i   = blockIdx.x;

    if (tid < 64) s_wp[tid] = g_wp[tid];
    else if (tid < 72)  s_b1p[tid - 64]  = g_b1p[tid - 64];
    else if (tid < 80)  s_gp[tid - 72]   = g_gp[tid - 72];
    else if (tid < 88)  s_btp[tid - 80]  = g_btp[tid - 80];
    else if (tid < 96)  s_w2gp[tid - 88] = g_w2gp[tid - 88];
    else if (tid < 104) s_w05p[tid - 96] = g_w05p[tid - 96];

    const float lg0 = ib2[0] + 0.5f * g_cL[0];

    const float4 ia  = g_pre4[i * 2 + 0];
    const float4 ibv = g_pre4[i * 2 + 1];
    const float ti = ia.x, rai = ia.y, dei = ia.z, mci = ia.w;
    const float fii = ibv.x, dii = ibv.y, psi = ibv.z;

    if (tid == 0) g_ew[(size_t)i * N + i] = 0.f;   // exp(-inf)

    // Hoisted packed constants
    const u64 ABSM = 0x7FFFFFFF7FFFFFFFULL;
    const u64 SGNM = 0x8000000080000000ULL;
    const u64 one2  = pk2(1.f, 1.f);
    const u64 isq2  = pk2(0.70710678118654752f, 0.70710678118654752f);
    const u64 pp2   = pk2(0.3275911f, 0.3275911f);
    const u64 nl2e  = pk2(-1.44269504088896f, -1.44269504088896f);
    const u64 cA5   = pk2(-1.061405429f, -1.061405429f);
    const u64 cA4   = pk2( 1.453152027f,  1.453152027f);
    const u64 cA3   = pk2(-1.421413741f, -1.421413741f);
    const u64 cA2   = pk2( 0.284496736f,  0.284496736f);
    const u64 cA1   = pk2(-0.254829592f, -0.254829592f);

    __syncthreads();

    for (int j = i + 1 + tid; j < N; j += TPB) {
        const float4 ja = g_pre4[j * 2 + 0];
        const float4 jb = g_pre4[j * 2 + 1];

        float dra = fabsf(rai - ja.y);
        float dde = fabsf(dei - ja.z);
        float f0 = fabsf(ti - ja.x);
        float ss = fmaxf(fmaf(dra, dra, dde * dde), 1e-30f);
        float f1 = ss * rsqrtf(ss);
        float f2 = rcpa(fmaf(fabsf(mci - ja.w), (1.f / 30.f), 1.f));
        float f3 = ex2a(-fabsf(fii - jb.x) * 0.0144269504f);
        float f4 = fminf(dii, jb.y) * rcpa(fmaxf(dii, jb.y));
        float f5 = fabsf(psi - jb.z);

        // Splat features
        u64 F[8];
        F[0] = pk2(f0, f0); F[1] = pk2(f1, f1); F[2] = pk2(f2, f2); F[3] = pk2(f3, f3);
        F[4] = pk2(f4, f4); F[5] = pk2(f5, f5); F[6] = pk2(dra, dra); F[7] = pk2(dde, dde);

        // Packed GEMV: acc[hp] = {zc[hp], zc[hp+8]}
        u64 acc[8];
#pragma unroll
        for (int hp = 0; hp < 8; hp++) acc[hp] = s_b1p[hp];
#pragma unroll
        for (int k = 0; k < 8; k++) {
#pragma unroll
            for (int hp = 0; hp < 8; hp++)
                acc[hp] = fma2(s_wp[k * 8 + hp], F[k], acc[hp]);
        }
        // Packed variance + folded linear dot
        u64 v2 = 0ULL, d2 = 0ULL;
#pragma unroll
        for (int hp = 0; hp < 8; hp++) {
            v2 = fma2(acc[hp], acc[hp], v2);
            d2 = fma2(s_w2gp[hp], acc[hp], d2);
        }
        float vlo, vhi, dlo, dhi;
        upk2(v2, vlo, vhi);
        upk2(d2, dlo, dhi);
        float var = vlo + vhi;
        float dot = dlo + dhi;
        float inv = rsqrtf(fmaf(var, (1.f / HID), 1e-5f));
        const u64 invp = pk2(inv, inv);

        // Packed erf epilogue: lgp accumulates 0.5*w2*xn*erf(xn/sqrt2)
        u64 lgp = 0ULL;
#pragma unroll
        for (int hp = 0; hp < 8; hp++) {
            u64 xnp = fma2(mul2(acc[hp], invp), s_gp[hp], s_btp[hp]);
            u64 axp = mul2(xnp & ABSM, isq2);
            u64 upre = fma2(pp2, axp, one2);
            float tlo, thi; upk2(upre, tlo, thi);
            u64 up = pk2(rcpa(tlo), rcpa(thi));
            u64 pl = fma2(cA5, up, cA4);
            pl = fma2(pl, up, cA3);
            pl = fma2(pl, up, cA2);
            pl = fma2(pl, up, cA1);
            pl = mul2(pl, up);                       // = -poly
            u64 marg = mul2(mul2(axp, axp), nl2e);   // -ax^2*log2e
            float mlo, mhi; upk2(marg, mlo, mhi);
            u64 ep = pk2(ex2a(mlo), ex2a(mhi));
            u64 er = fma2(pl, ep, one2);             // 1 - poly*e  (positive)
            er = er | (xnp & SGNM);                  // copysign
            lgp = fma2(s_w05p[hp], mul2(xnp, er), lgp);
        }
        float llo, lhi; upk2(lgp, llo, lhi);
        float lg = llo + lhi + fmaf(0.5f * inv, dot, lg0);

        float e = __expf(lg);
        g_ew[(size_t)i * N + j] = e;   // coalesced
        g_ew[(size_t)j * N + i] = e;   // scattered mirror (hidden under compute)
    }
}

// ---------------------------------------------------------------------------
// Kernel C: per-row sum + weighted features + overlap net.
// ---------------------------------------------------------------------------
__global__ __launch_bounds__(TPB) void row2_kernel(
    const float* __restrict__ ow1, const float* __restrict__ ob1,
    const float* __restrict__ og1, const float* __restrict__ obt1,
    const float* __restrict__ ow2, const float* __restrict__ ob2,
    float* __restrict__ out)
{
    __shared__ float s_red[8];
    __shared__ float s_red8[8][8];
    __shared__ float s_bcast[1];
    __shared__ float s_wsum[8];
    __shared__ float s_h2[32];

    const int tid  = threadIdx.x;
    const int i    = blockIdx.x;
    const int lane = tid & 31;
    const int wid  = tid >> 5;

    const float4 ia  = g_pre4[i * 2 + 0];
    const float4 ibv = g_pre4[i * 2 + 1];
    const float ti = ia.x, rai = ia.y, dei = ia.z, mci = ia.w;
    const float fii = ibv.x, dii = ibv.y, psi = ibv.z;

    float e[8];
    const float* rowp = g_ew + (size_t)i * N;
    float lsum = 0.f;
#pragma unroll
    for (int jj = 0; jj < 8; jj++) {
        e[jj] = rowp[(jj << 8) | tid];
        lsum += e[jj];
    }
#pragma unroll
    for (int o = 16; o; o >>= 1) lsum += __shfl_xor_sync(0xFFFFFFFFu, lsum, o);
    if (lane == 0) s_red[wid] = lsum;
    __syncthreads();
    if (wid == 0) {
        float s = s_red[lane & 7];
#pragma unroll
        for (int o = 4; o; o >>= 1) s += __shfl_xor_sync(0xFFFFFFFFu, s, o);
        if (lane == 0) s_bcast[0] = 1.f / s;
    }

    float acc0 = 0, acc1 = 0, acc2 = 0, acc3 = 0, acc4 = 0, acc5 = 0, acc6 = 0, acc7 = 0;
#pragma unroll
    for (int jj = 0; jj < 8; jj++) {
        const int j = (jj << 8) | tid;
        const float w = e[jj];
        const float4 ja = g_pre4[j * 2 + 0];
        const float4 jb = g_pre4[j * 2 + 1];
        float dra = fabsf(rai - ja.y);
        float dde = fabsf(dei - ja.z);
        float ss = fmaxf(fmaf(dra, dra, dde * dde), 1e-30f);
        acc0 = fmaf(w, fabsf(ti - ja.x), acc0);
        acc1 = fmaf(w, ss * rsqrtf(ss), acc1);
        acc2 = fmaf(w, rcpa(fmaf(fabsf(mci - ja.w), (1.f / 30.f), 1.f)), acc2);
        acc3 = fmaf(w, ex2a(-fabsf(fii - jb.x) * 0.0144269504f), acc3);
        acc4 = fmaf(w, fminf(dii, jb.y) * rcpa(fmaxf(dii, jb.y)), acc4);
        acc5 = fmaf(w, fabsf(psi - jb.z), acc5);
        acc6 = fmaf(w, dra, acc6);
        acc7 = fmaf(w, dde, acc7);
    }
    float accs[8] = {acc0, acc1, acc2, acc3, acc4, acc5, acc6, acc7};
#pragma unroll
    for (int f = 0; f < 8; f++) {
        float v = accs[f];
#pragma unroll
        for (int o = 16; o; o >>= 1) v += __shfl_xor_sync(0xFFFFFFFFu, v, o);
        if (lane == 0) s_red8[wid][f] = v;
    }
    __syncthreads();
    if (tid < 8) {
        float v = 0.f;
#pragma unroll
        for (int w = 0; w < 8; w++) v += s_red8[w][tid];
        s_wsum[tid] = v * s_bcast[0];
    }
    __syncthreads();

    if (tid < 32) {
        float a = ob1[tid];
#pragma unroll
        for (int f = 0; f < 8; f++) a = fmaf(ow1[tid * 8 + f], s_wsum[f], a);
        float s = a;
#pragma unroll
        for (int o = 16; o; o >>= 1) s += __shfl_xor_sync(0xFFFFFFFFu, s, o);
        float mu = s * (1.f / 32.f);
        float d = a - mu;
        float v = d * d;
#pragma unroll
        for (int o = 16; o; o >>= 1) v += __shfl_xor_sync(0xFFFFFFFFu, v, o);
        float invs = rsqrtf(fmaf(v, (1.f / 32.f), 1e-5f));
        float xn = fmaf(d * invs, og1[tid], obt1[tid]);
        s_h2[tid] = gelu_fast(xn);
        __syncwarp();
        if (tid < 16) {
            float o_ = ob2[tid];
#pragma unroll
            for (int k = 0; k < 32; k++) o_ = fmaf(ow2[tid * 32 + k], s_h2[k], o_);
            out[i * 16 + tid] = o_;
        }
    }
}

extern "C" void kernel_launch(void* const* d_in, const int* in_sizes, int n_in,
                              void* d_out, int out_size) {
    const float* params = (const float*)d_in[0];
    const float* iw1  = (const float*)d_in[1];
    const float* ib1  = (const float*)d_in[2];
    const float* ig1  = (const float*)d_in[3];
    const float* ibt1 = (const float*)d_in[4];
    const float* iw2  = (const float*)d_in[5];
    const float* ib2  = (const float*)d_in[6];
    const float* ow1  = (const float*)d_in[7];
    const float* ob1  = (const float*)d_in[8];
    const float* og1  = (const float*)d_in[9];
    const float* obt1 = (const float*)d_in[10];
    const float* ow2  = (const float*)d_in[11];
    const float* ob2  = (const float*)d_in[12];
    float* out = (float*)d_out;

    pre_kernel<<<(N + 255) / 256, 256>>>(params, iw1, ib1, ig1, ibt1, iw2);
    logits_kernel<<<N, TPB>>>(ib2);
    row2_kernel<<<N, TPB>>>(ow1, ob1, og1, obt1, ow2, ob2, out);
}

// round 7
// speedup vs baseline: 1.2221x; 1.2221x over previous
#include <cuda_runtime.h>
#include <math.h>

#define N    2048
#define HID  16
#define TPB  256
#define T    32
#define NT   (N / T)               // 64
#define NBLK (NT * (NT + 1) / 2)   // 2080

// Per-signal derived scalars: [i*2+0]={t,ra,dec,mc}  [i*2+1]={f_isco,dist,psi,0}
__device__ float4 g_pre4[2 * N];
// Accumulators per row: {sum_e, sum_e*f0 .. sum_e*f7}
__device__ float g_acc[N * 9];
// Preprocessed importance-net weights (W1c = W1 - colmean, b1c = b1 - mean(b1)):
// g_wA[h]=W1c[h][0..3], g_wB[h]=W1c[h][4..7], g_pp[h]={g1, bt1, 0.5*w2, b1c}
__device__ float4 g_wA[HID], g_wB[HID], g_pp[HID];
__device__ float g_w2g[HID];   // w2*g1 (folded linear dot)
__device__ float g_cL[1];      // sum_h w2*bt1

__device__ __forceinline__ float rcpa(float x) {
    float r; asm("rcp.approx.f32 %0, %1;" : "=f"(r) : "f"(x)); return r;
}
__device__ __forceinline__ float ex2a(float x) {
    float r; asm("ex2.approx.f32 %0, %1;" : "=f"(r) : "f"(x)); return r;
}

// ---------------------------------------------------------------------------
// Pre: per-signal scalars (blocks 0-63), weight prep (block 64), acc zeroing.
// ---------------------------------------------------------------------------
__global__ void pre_kernel(const float* __restrict__ p,
                           const float* __restrict__ iw1, const float* __restrict__ ib1,
                           const float* __restrict__ ig1, const float* __restrict__ ibt1,
                           const float* __restrict__ iw2)
{
    int tid = threadIdx.x;
    int b   = blockIdx.x;
    if (b < 64) {
        int i = b * 32 + tid;
        const float* pi = p + i * 15;
        float m1 = fmaf(pi[0], 95.f, 5.f);
        float m2 = fmaf(pi[1], 95.f, 5.f);
        float mc = __powf(m1 * m2, 0.6f) * __powf(m1 + m2, -0.2f);
        g_pre4[i * 2 + 0] = make_float4(pi[5], pi[3], pi[4], mc);
        g_pre4[i * 2 + 1] = make_float4(220.f / (m1 + m2), fmaf(pi[2], 2950.f, 50.f), pi[7], 0.f);
        // zero accumulators (9 floats per signal)
        float* za = g_acc + (size_t)i * 9;
#pragma unroll
        for (int k = 0; k < 9; k++) za[k] = 0.f;
    } else {
        __shared__ float s_col[8];
        __shared__ float s_bm;
        if (tid < 8) {
            float s = 0.f;
#pragma unroll
            for (int h = 0; h < HID; h++) s += iw1[h * 8 + tid];
            s_col[tid] = s * (1.f / HID);
        }
        if (tid == 0) {
            float bm = 0.f, cl = 0.f;
#pragma unroll
            for (int h = 0; h < HID; h++) { bm += ib1[h]; cl += iw2[h] * ibt1[h]; }
            s_bm = bm * (1.f / HID);
            g_cL[0] = cl;
        }
        __syncthreads();
        if (tid < HID) {
            int h = tid;
            g_wA[h] = make_float4(iw1[h*8+0] - s_col[0], iw1[h*8+1] - s_col[1],
                                  iw1[h*8+2] - s_col[2], iw1[h*8+3] - s_col[3]);
            g_wB[h] = make_float4(iw1[h*8+4] - s_col[4], iw1[h*8+5] - s_col[5],
                                  iw1[h*8+6] - s_col[6], iw1[h*8+7] - s_col[7]);
            g_pp[h] = make_float4(ig1[h], ibt1[h], 0.5f * iw2[h], ib1[h] - s_bm);
            g_w2g[h] = iw2[h] * ig1[h];
        }
    }
}

// ---------------------------------------------------------------------------
// Pair kernel: 32x32 tiles, triangular grid. Computes e=exp(logit) per pair,
// accumulates {e, e*f0..e*f7} into BOTH row-i and row-j accumulators.
// ---------------------------------------------------------------------------
__global__ __launch_bounds__(TPB) void pair_kernel(const float* __restrict__ ib2)
{
    __shared__ float4 s_wA[HID], s_wB[HID], s_pp[HID];
    __shared__ float  s_w2g[HID];
    __shared__ float  s_ipre[7][T];
    __shared__ float  s_jred[8][T][9];

    const int tid  = threadIdx.x;
    const int lane = tid & 31;
    const int wg   = tid >> 5;

    // Triangular decode: blocks enumerate (ti, tj) with tj >= ti.
    int b = blockIdx.x;
    int ti = (int)((2.f * NT + 1.f - sqrtf((2.f * NT + 1.f) * (2.f * NT + 1.f) - 8.f * (float)b)) * 0.5f);
    if (ti >= NT) ti = NT - 1;
    while (ti > 0 && (ti * NT - ti * (ti - 1) / 2) > b) ti--;
    while (((ti + 1) * NT - (ti + 1) * ti / 2) <= b) ti++;
    const int tj = ti + (b - (ti * NT - ti * (ti - 1) / 2));
    const bool diag = (ti == tj);

    if (tid < HID)            s_wA[tid]        = g_wA[tid];
    else if (tid < 2*HID)     s_wB[tid-HID]    = g_wB[tid-HID];
    else if (tid < 3*HID)     s_pp[tid-2*HID]  = g_pp[tid-2*HID];
    else if (tid < 4*HID)     s_w2g[tid-3*HID] = g_w2g[tid-3*HID];
    else if (tid >= 128 && tid < 160) {
        int r = tid - 128;
        int ii = ti * T + r;
        float4 a = g_pre4[ii * 2 + 0];
        float4 c = g_pre4[ii * 2 + 1];
        s_ipre[0][r] = a.x; s_ipre[1][r] = a.y; s_ipre[2][r] = a.z;
        s_ipre[3][r] = a.w; s_ipre[4][r] = c.x; s_ipre[5][r] = c.y;
        s_ipre[6][r] = c.z;
    }

    const float lg0 = ib2[0] + 0.5f * g_cL[0];

    // j-side scalars in registers for the whole block
    const int j = tj * T + lane;
    const float4 ja = g_pre4[j * 2 + 0];
    const float4 jb = g_pre4[j * 2 + 1];
    const float tj_ = ja.x, raj = ja.y, dej = ja.z, mcj = ja.w;
    const float fij = jb.x, dij = jb.y, psj = jb.z;

    float jacc[9];
#pragma unroll
    for (int k = 0; k < 9; k++) jacc[k] = 0.f;

    __syncthreads();

#pragma unroll
    for (int m = 0; m < 4; m++) {
        const int r = (m << 3) + wg;
        const int i = ti * T + r;
        float v[9];
        const bool valid = (!diag) || (j > i);
        if (valid) {
            const float ti_ = s_ipre[0][r], rai = s_ipre[1][r], dei = s_ipre[2][r];
            const float mci = s_ipre[3][r], fii = s_ipre[4][r], dii = s_ipre[5][r];
            const float psi = s_ipre[6][r];

            float dra = fabsf(rai - raj);
            float dde = fabsf(dei - dej);
            float f0 = fabsf(ti_ - tj_);
            float ss = fmaxf(fmaf(dra, dra, dde * dde), 1e-30f);
            float f1 = ss * rsqrtf(ss);
            float f2 = rcpa(fmaf(fabsf(mci - mcj), (1.f / 30.f), 1.f));
            float f3 = ex2a(-fabsf(fii - fij) * 0.0144269504f);
            float f4 = fminf(dii, dij) * rcpa(fmaxf(dii, dij));
            float f5 = fabsf(psi - psj);

            float zc[HID];
            float var = 0.f, dot = 0.f;
#pragma unroll
            for (int h = 0; h < HID; h++) {
                float4 wa = s_wA[h];
                float4 wb = s_wB[h];
                float a = s_pp[h].w;               // b1c
                a = fmaf(wa.x, f0, a); a = fmaf(wa.y, f1, a);
                a = fmaf(wa.z, f2, a); a = fmaf(wa.w, f3, a);
                a = fmaf(wb.x, f4, a); a = fmaf(wb.y, f5, a);
                a = fmaf(wb.z, dra, a); a = fmaf(wb.w, dde, a);
                zc[h] = a;
                var = fmaf(a, a, var);
                dot = fmaf(s_w2g[h], a, dot);
            }
            float inv = rsqrtf(fmaf(var, (1.f / HID), 1e-5f));
            float lg = fmaf(0.5f * inv, dot, lg0);
#pragma unroll
            for (int h = 0; h < HID; h++) {
                float4 pp = s_pp[h];
                float xn = fmaf(zc[h] * inv, pp.x, pp.y);
                float ax = fabsf(xn) * 0.70710678118654752f;
                float u  = rcpa(fmaf(0.3275911f, ax, 1.f));
                float pl = fmaf(fmaf(fmaf(fmaf(1.061405429f, u, -1.453152027f),
                                           u, 1.421413741f),
                                      u, -0.284496736f),
                                 u, 0.254829592f) * u;
                float e_ = ex2a(-0.72134752044448f * (xn * xn));
                float er = fmaf(-pl, e_, 1.f);
                er = copysignf(er, xn);
                lg = fmaf(pp.z * xn, er, lg);     // 0.5*w2*xn*erf
            }
            float e = ex2a(lg * 1.44269504088896f);

            v[0] = e;
            v[1] = e * f0; v[2] = e * f1; v[3] = e * f2; v[4] = e * f3;
            v[5] = e * f4; v[6] = e * f5; v[7] = e * dra; v[8] = e * dde;
#pragma unroll
            for (int k = 0; k < 9; k++) jacc[k] += v[k];
        } else {
#pragma unroll
            for (int k = 0; k < 9; k++) v[k] = 0.f;
        }
        // Row-side: warp reduce (warp covers all 32 j for row i), lane0 atomics
#pragma unroll
        for (int k = 0; k < 9; k++) {
            float x = v[k];
#pragma unroll
            for (int o = 16; o; o >>= 1) x += __shfl_xor_sync(0xFFFFFFFFu, x, o);
            if (lane == 0) atomicAdd(&g_acc[(size_t)i * 9 + k], x);
        }
    }

    // Col-side: per-thread register acc -> smem -> 32-thread reduce + atomics
#pragma unroll
    for (int k = 0; k < 9; k++) s_jred[wg][lane][k] = jacc[k];
    __syncthreads();
    if (tid < 32) {
        const int jj = tj * T + tid;
#pragma unroll
        for (int k = 0; k < 9; k++) {
            float s = 0.f;
#pragma unroll
            for (int w = 0; w < 8; w++) s += s_jred[w][tid][k];
            atomicAdd(&g_acc[(size_t)jj * 9 + k], s);
        }
    }
}

// ---------------------------------------------------------------------------
// Final: normalize + overlap net. One warp per row.
// ---------------------------------------------------------------------------
__global__ __launch_bounds__(TPB) void final_kernel(
    const float* __restrict__ ow1, const float* __restrict__ ob1,
    const float* __restrict__ og1, const float* __restrict__ obt1,
    const float* __restrict__ ow2, const float* __restrict__ ob2,
    float* __restrict__ out)
{
    __shared__ float s_h2[8][32];
    const int tid  = threadIdx.x;
    const int lane = tid & 31;
    const int wid  = tid >> 5;
    const int row  = blockIdx.x * 8 + wid;

    float myv = (lane < 9) ? g_acc[(size_t)row * 9 + lane] : 0.f;
    float invS = rcpa(__shfl_sync(0xFFFFFFFFu, myv, 0));

    // hidden unit = lane (32 units)
    float a = ob1[lane];
#pragma unroll
    for (int f = 0; f < 8; f++)
        a = fmaf(ow1[lane * 8 + f], __shfl_sync(0xFFFFFFFFu, myv, f + 1) * invS, a);

    float s = a;
#pragma unroll
    for (int o = 16; o; o >>= 1) s += __shfl_xor_sync(0xFFFFFFFFu, s, o);
    float mu = s * (1.f / 32.f);
    float d = a - mu;
    float v = d * d;
#pragma unroll
    for (int o = 16; o; o >>= 1) v += __shfl_xor_sync(0xFFFFFFFFu, v, o);
    float invs = rsqrtf(fmaf(v, (1.f / 32.f), 1e-5f));
    float xn = fmaf(d * invs, og1[lane], obt1[lane]);

    // erf GELU (accurate form via AS 7.1.26)
    float ax = fabsf(xn) * 0.70710678118654752f;
    float u  = rcpa(fmaf(0.3275911f, ax, 1.f));
    float pl = fmaf(fmaf(fmaf(fmaf(1.061405429f, u, -1.453152027f),
                               u, 1.421413741f),
                          u, -0.284496736f),
                     u, 0.254829592f) * u;
    float e_ = ex2a(-1.44269504088896f * (ax * ax));
    float er = fmaf(-pl, e_, 1.f);
    er = copysignf(er, xn);
    s_h2[wid][lane] = 0.5f * xn * (1.f + er);
    __syncwarp();

    if (lane < 16) {
        float o_ = ob2[lane];
#pragma unroll
        for (int k = 0; k < 32; k++) o_ = fmaf(ow2[lane * 32 + k], s_h2[wid][k], o_);
        out[row * 16 + lane] = o_;
    }
}

extern "C" void kernel_launch(void* const* d_in, const int* in_sizes, int n_in,
                              void* d_out, int out_size) {
    const float* params = (const float*)d_in[0];
    const float* iw1  = (const float*)d_in[1];
    const float* ib1  = (const float*)d_in[2];
    const float* ig1  = (const float*)d_in[3];
    const float* ibt1 = (const float*)d_in[4];
    const float* iw2  = (const float*)d_in[5];
    const float* ib2  = (const float*)d_in[6];
    const float* ow1  = (const float*)d_in[7];
    const float* ob1  = (const float*)d_in[8];
    const float* og1  = (const float*)d_in[9];
    const float* obt1 = (const float*)d_in[10];
    const float* ow2  = (const float*)d_in[11];
    const float* ob2  = (const float*)d_in[12];
    float* out = (float*)d_out;

    pre_kernel<<<65, 32>>>(params, iw1, ib1, ig1, ibt1, iw2);
    pair_kernel<<<NBLK, TPB>>>(ib2);
    final_kernel<<<N / 8, TPB>>>(ow1, ob1, og1, obt1, ow2, ob2, out);
}